// round 2
// baseline (speedup 1.0000x reference)
#include <cuda_runtime.h>
#include <math.h>

// Problem constants (fixed by the reference)
#define T_TOK 16384      // BATCH * SEQ
#define D_IN  1024
#define D_OUT 1024
#define N_EXP 8
#define RANK  32
#define ER    256        // N_EXP * RANK
#define NCAT  1280       // D_OUT + ER

// ---------------- device scratch (no allocations allowed) ----------------
__device__ float g_Wcat[NCAT * D_IN];     // rows 0..1023 = base_W, 1024..1279 = A*sigmoid(S_a)
__device__ float g_Bcat[D_OUT * ER];      // [o][e*RANK+r] = B*sigmoid(S_b)
__device__ float g_H[T_TOK * ER];         // gated low-rank activations
__device__ float g_gate[T_TOK * N_EXP];   // dense top-2 gate matrix

// ---------------- prep: build Wcat / Bcat with sigmoid masks ----------------
__global__ void prep_kernel(const float* __restrict__ base_W,
                            const float* __restrict__ A,
                            const float* __restrict__ S_a,
                            const float* __restrict__ B,
                            const float* __restrict__ S_b) {
    const int totalW  = D_OUT * D_IN;          // 1048576
    const int totalA  = ER * D_IN;             // 262144
    const int totalB  = N_EXP * D_OUT * RANK;  // 262144
    const int total   = totalW + totalA + totalB;
    for (int idx = blockIdx.x * blockDim.x + threadIdx.x; idx < total;
         idx += gridDim.x * blockDim.x) {
        if (idx < totalW) {
            g_Wcat[idx] = base_W[idx];
        } else if (idx < totalW + totalA) {
            int i = idx - totalW;              // A is [E, R, D_IN]: row (e*R+r), col d — matches Wcat tail
            float s = S_a[i];
            float sig = 1.0f / (1.0f + expf(-s));
            g_Wcat[totalW + i] = A[i] * sig;
        } else {
            int i = idx - totalW - totalA;     // B is [E, D_OUT, R]
            int e   = i / (D_OUT * RANK);
            int rem = i - e * (D_OUT * RANK);
            int o   = rem / RANK;
            int r   = rem - o * RANK;
            float s = S_b[i];
            float sig = 1.0f / (1.0f + expf(-s));
            g_Bcat[o * ER + e * RANK + r] = B[i] * sig;
        }
    }
}

// ---------------- router: logits -> softmax -> top-2 dense gate ----------------
__global__ void router_kernel(const float4* __restrict__ x4,
                              const float4* __restrict__ rw4,
                              const float* __restrict__ router_b) {
    const int warp = (blockIdx.x * blockDim.x + threadIdx.x) >> 5;
    const int lane = threadIdx.x & 31;
    if (warp >= T_TOK) return;

    float acc[N_EXP];
#pragma unroll
    for (int e = 0; e < N_EXP; e++) acc[e] = 0.0f;

    const float4* xrow = x4 + (size_t)warp * (D_IN / 4);
#pragma unroll 4
    for (int j = lane; j < D_IN / 4; j += 32) {
        float4 xv = xrow[j];
#pragma unroll
        for (int e = 0; e < N_EXP; e++) {
            float4 wv = rw4[e * (D_IN / 4) + j];
            acc[e] += xv.x * wv.x + xv.y * wv.y + xv.z * wv.z + xv.w * wv.w;
        }
    }
#pragma unroll
    for (int e = 0; e < N_EXP; e++) {
#pragma unroll
        for (int off = 16; off; off >>= 1)
            acc[e] += __shfl_xor_sync(0xffffffffu, acc[e], off);
        acc[e] += router_b[e];
    }

    // softmax over 8 (all lanes redundantly — cheap)
    float mx = acc[0];
#pragma unroll
    for (int e = 1; e < N_EXP; e++) mx = fmaxf(mx, acc[e]);
    float p[N_EXP];
    float sum = 0.0f;
#pragma unroll
    for (int e = 0; e < N_EXP; e++) { p[e] = expf(acc[e] - mx); sum += p[e]; }
    float inv = 1.0f / sum;

    // top-2 (strict > keeps lowest index on ties, matching lax.top_k)
    int i1 = 0; float v1 = p[0];
#pragma unroll
    for (int e = 1; e < N_EXP; e++) if (p[e] > v1) { v1 = p[e]; i1 = e; }
    int i2 = -1; float v2 = -1.0f;
#pragma unroll
    for (int e = 0; e < N_EXP; e++) if (e != i1 && p[e] > v2) { v2 = p[e]; i2 = e; }

    if (lane < N_EXP) {
        float g = (lane == i1) ? v1 * inv : (lane == i2) ? v2 * inv : 0.0f;
        g_gate[warp * N_EXP + lane] = g;
    }
}

// ---------------- tiled SGEMM: C = Arow[M,K] @ Brow[N,K]^T ----------------
// Double-buffered smem + register staging: global loads for slice k+1 issue
// before the FMA loop over slice k, so DRAM/L2 latency overlaps compute.
// MODE 0: A = x, B = g_Wcat, N=1280, K=1024.
//         cols <1024 -> d_out = acc + bias ; cols >=1024 -> g_H = acc * gate
// MODE 1: A = g_H, B = g_Bcat, N=1024, K=256.  d_out += acc
#define BM 128
#define BN 128
#define BK 16

template <int MODE>
__global__ void __launch_bounds__(256)
gemm_kernel(const float* __restrict__ Ain,
            const float* __restrict__ bias,
            float* __restrict__ Cout) {
    const float* __restrict__ Ag = (MODE == 0) ? Ain : g_H;
    const float* __restrict__ Bg = (MODE == 0) ? g_Wcat : g_Bcat;
    const int K = (MODE == 0) ? 1024 : 256;

    __shared__ float As[2][BK][BM];   // transposed: As[buf][k][m]
    __shared__ float Bs[2][BK][BN];   // Bs[buf][k][n]

    const int tid = threadIdx.x;
    const int tx = tid & 15;       // 0..15 -> n microtile
    const int ty = tid >> 4;       // 0..15 -> m microtile
    const int m0 = blockIdx.y * BM;
    const int n0 = blockIdx.x * BN;

    // Each thread owns 2 float4 slots per operand tile (512 slots / 256 thr).
    // slot s (0/1): v = tid + s*256 ; r = v>>2 (row 0..127) ; c = (v&3)*4.
    int ldr[2], ldc[2];
#pragma unroll
    for (int s = 0; s < 2; s++) {
        int v = tid + s * 256;
        ldr[s] = v >> 2;
        ldc[s] = (v & 3) * 4;
    }

    float acc[8][8];
#pragma unroll
    for (int i = 0; i < 8; i++)
#pragma unroll
        for (int j = 0; j < 8; j++) acc[i][j] = 0.0f;

    float4 ar[2], br[2];

    // ---- prologue: load slice 0 into registers, store to buffer 0 ----
#pragma unroll
    for (int s = 0; s < 2; s++) {
        ar[s] = *(const float4*)(Ag + (size_t)(m0 + ldr[s]) * K + ldc[s]);
        br[s] = *(const float4*)(Bg + (size_t)(n0 + ldr[s]) * K + ldc[s]);
    }
#pragma unroll
    for (int s = 0; s < 2; s++) {
        As[0][ldc[s] + 0][ldr[s]] = ar[s].x; As[0][ldc[s] + 1][ldr[s]] = ar[s].y;
        As[0][ldc[s] + 2][ldr[s]] = ar[s].z; As[0][ldc[s] + 3][ldr[s]] = ar[s].w;
        Bs[0][ldc[s] + 0][ldr[s]] = br[s].x; Bs[0][ldc[s] + 1][ldr[s]] = br[s].y;
        Bs[0][ldc[s] + 2][ldr[s]] = br[s].z; Bs[0][ldc[s] + 3][ldr[s]] = br[s].w;
    }
    __syncthreads();

    int buf = 0;
    for (int k0 = 0; k0 < K; k0 += BK) {
        // ---- prefetch slice k0+BK into registers (overlaps FMA loop) ----
        const bool has_next = (k0 + BK) < K;
        if (has_next) {
            int kn = k0 + BK;
#pragma unroll
            for (int s = 0; s < 2; s++) {
                ar[s] = *(const float4*)(Ag + (size_t)(m0 + ldr[s]) * K + kn + ldc[s]);
                br[s] = *(const float4*)(Bg + (size_t)(n0 + ldr[s]) * K + kn + ldc[s]);
            }
        }

        // ---- compute on current buffer ----
#pragma unroll
        for (int kk = 0; kk < BK; kk++) {
            float4 a0 = *(const float4*)&As[buf][kk][ty * 8];
            float4 a1 = *(const float4*)&As[buf][kk][ty * 8 + 4];
            float4 b0 = *(const float4*)&Bs[buf][kk][tx * 8];
            float4 b1 = *(const float4*)&Bs[buf][kk][tx * 8 + 4];
            float a[8] = {a0.x, a0.y, a0.z, a0.w, a1.x, a1.y, a1.z, a1.w};
            float b[8] = {b0.x, b0.y, b0.z, b0.w, b1.x, b1.y, b1.z, b1.w};
#pragma unroll
            for (int i = 0; i < 8; i++)
#pragma unroll
                for (int j = 0; j < 8; j++)
                    acc[i][j] = fmaf(a[i], b[j], acc[i][j]);
        }

        // ---- store prefetched regs into the other buffer ----
        if (has_next) {
            int nb = buf ^ 1;
#pragma unroll
            for (int s = 0; s < 2; s++) {
                As[nb][ldc[s] + 0][ldr[s]] = ar[s].x; As[nb][ldc[s] + 1][ldr[s]] = ar[s].y;
                As[nb][ldc[s] + 2][ldr[s]] = ar[s].z; As[nb][ldc[s] + 3][ldr[s]] = ar[s].w;
                Bs[nb][ldc[s] + 0][ldr[s]] = br[s].x; Bs[nb][ldc[s] + 1][ldr[s]] = br[s].y;
                Bs[nb][ldc[s] + 2][ldr[s]] = br[s].z; Bs[nb][ldc[s] + 3][ldr[s]] = br[s].w;
            }
            __syncthreads();
            buf = nb;
        }
    }

    // ---------------- epilogue ----------------
    if (MODE == 0) {
        if (n0 < D_OUT) {
            // base part: d_out = acc + bias
#pragma unroll
            for (int i = 0; i < 8; i++) {
                int m = m0 + ty * 8 + i;
#pragma unroll
                for (int j4 = 0; j4 < 8; j4 += 4) {
                    int n = n0 + tx * 8 + j4;
                    float4 bb = *(const float4*)(bias + n);
                    float4 o;
                    o.x = acc[i][j4 + 0] + bb.x;
                    o.y = acc[i][j4 + 1] + bb.y;
                    o.z = acc[i][j4 + 2] + bb.z;
                    o.w = acc[i][j4 + 3] + bb.w;
                    *(float4*)(Cout + (size_t)m * D_OUT + n) = o;
                }
            }
        } else {
            // LoRA H part: g_H = acc * gate   (er = n - D_OUT)
            int erbase = n0 - D_OUT + tx * 8;   // 8-wide microtile stays inside one expert's 32-col group
            int egrp = erbase >> 5;             // which expert's gate
#pragma unroll
            for (int i = 0; i < 8; i++) {
                int m = m0 + ty * 8 + i;
                float g = g_gate[m * N_EXP + egrp];
#pragma unroll
                for (int j4 = 0; j4 < 8; j4 += 4) {
                    float4 o;
                    o.x = acc[i][j4 + 0] * g;
                    o.y = acc[i][j4 + 1] * g;
                    o.z = acc[i][j4 + 2] * g;
                    o.w = acc[i][j4 + 3] * g;
                    *(float4*)(g_H + (size_t)m * ER + erbase + j4) = o;
                }
            }
        }
    } else {
        // MODE 1: accumulate delta into d_out
#pragma unroll
        for (int i = 0; i < 8; i++) {
            int m = m0 + ty * 8 + i;
#pragma unroll
            for (int j4 = 0; j4 < 8; j4 += 4) {
                int n = n0 + tx * 8 + j4;
                float4 o = *(const float4*)(Cout + (size_t)m * D_OUT + n);
                o.x += acc[i][j4 + 0];
                o.y += acc[i][j4 + 1];
                o.z += acc[i][j4 + 2];
                o.w += acc[i][j4 + 3];
                *(float4*)(Cout + (size_t)m * D_OUT + n) = o;
            }
        }
    }
}

// ---------------- launcher ----------------
extern "C" void kernel_launch(void* const* d_in, const int* in_sizes, int n_in,
                              void* d_out, int out_size) {
    const float* x        = (const float*)d_in[0];
    const float* base_W   = (const float*)d_in[1];
    const float* base_b   = (const float*)d_in[2];
    const float* router_W = (const float*)d_in[3];
    const float* router_b = (const float*)d_in[4];
    const float* A        = (const float*)d_in[5];
    const float* S_a      = (const float*)d_in[6];
    const float* B        = (const float*)d_in[7];
    const float* S_b      = (const float*)d_in[8];
    float* out = (float*)d_out;

    // 1) build masked/concatenated weights
    prep_kernel<<<1536, 512>>>(base_W, A, S_a, B, S_b);

    // 2) router -> dense gate matrix (one warp per token)
    router_kernel<<<T_TOK / 8, 256>>>((const float4*)x, (const float4*)router_W, router_b);

    // 3) fused GEMM: [base_out | H] = X @ [W ; A_t]^T ; H gated in epilogue
    gemm_kernel<0><<<dim3(NCAT / BN, T_TOK / BM), 256>>>(x, base_b, out);

    // 4) delta GEMM: d_out += G @ Bcat^T
    gemm_kernel<1><<<dim3(D_OUT / BN, T_TOK / BM), 256>>>(nullptr, nullptr, out);
}

// round 4
// speedup vs baseline: 2.8876x; 2.8876x over previous
#include <cuda_runtime.h>
#include <cuda_bf16.h>
#include <math.h>
#include <stdint.h>

// ---------------- problem constants ----------------
#define T_TOK 16384      // BATCH * SEQ
#define D_IN  1024
#define D_OUT 1024
#define N_EXP 8
#define RANK  32
#define ER    256        // N_EXP * RANK
#define NCAT  1280       // D_OUT + ER

// ---------------- device scratch (static; no allocations) ----------------
__device__ __nv_bfloat16 g_Whi[NCAT * D_IN];   // [W ; A*sig(S_a)] hi
__device__ __nv_bfloat16 g_Wlo[NCAT * D_IN];   // lo residual (base rows matter; A rows unused)
__device__ __nv_bfloat16 g_Bh [D_OUT * ER];    // B*sig(S_b) bf16, [o][e*R+r]
__device__ __nv_bfloat16 g_Xhi[T_TOK * D_IN];
__device__ __nv_bfloat16 g_Xlo[T_TOK * D_IN];
__device__ __nv_bfloat16 g_H  [T_TOK * ER];    // gated low-rank activations (bf16)
__device__ float         g_gate[T_TOK * N_EXP];

// ---------------- PTX helpers (sm_80-baseline ISA only!) ----------------
__device__ __forceinline__ uint32_t smem_u32(const void* p) {
    uint32_t a;
    asm("{ .reg .u64 t; cvta.to.shared.u64 t, %1; cvt.u32.u64 %0, t; }"
        : "=r"(a) : "l"(p));
    return a;
}

__device__ __forceinline__ void cp16(uint32_t s, const void* g) {
    asm volatile("cp.async.cg.shared.global [%0], [%1], 16;" :: "r"(s), "l"(g) : "memory");
}
#define CP_COMMIT() asm volatile("cp.async.commit_group;" ::: "memory")
#define CP_WAIT1()  asm volatile("cp.async.wait_group 1;" ::: "memory")

__device__ __forceinline__ void ldsm4(uint32_t* r, uint32_t addr) {
    asm volatile("ldmatrix.sync.aligned.m8n8.x4.shared.b16 {%0,%1,%2,%3}, [%4];"
                 : "=r"(r[0]), "=r"(r[1]), "=r"(r[2]), "=r"(r[3]) : "r"(addr));
}

__device__ __forceinline__ void mma_bf16(float* c, const uint32_t* a, const uint32_t* b) {
    asm volatile(
        "mma.sync.aligned.m16n8k16.row.col.f32.bf16.bf16.f32 "
        "{%0,%1,%2,%3}, {%4,%5,%6,%7}, {%8,%9}, {%0,%1,%2,%3};"
        : "+f"(c[0]), "+f"(c[1]), "+f"(c[2]), "+f"(c[3])
        : "r"(a[0]), "r"(a[1]), "r"(a[2]), "r"(a[3]), "r"(b[0]), "r"(b[1]));
}

// ---------------- prep: weights -> bf16 (hi/lo for W, hi for Bcat) ----------------
__global__ void prep_kernel(const float* __restrict__ base_W,
                            const float* __restrict__ A,
                            const float* __restrict__ S_a,
                            const float* __restrict__ B,
                            const float* __restrict__ S_b) {
    const int totalW = D_OUT * D_IN;           // 1048576
    const int totalA = ER * D_IN;              // 262144
    const int totalB = N_EXP * D_OUT * RANK;   // 262144
    const int total  = totalW + totalA + totalB;
    for (int idx = blockIdx.x * blockDim.x + threadIdx.x; idx < total;
         idx += gridDim.x * blockDim.x) {
        if (idx < totalW) {
            float v = base_W[idx];
            __nv_bfloat16 h = __float2bfloat16_rn(v);
            g_Whi[idx] = h;
            g_Wlo[idx] = __float2bfloat16_rn(v - __bfloat162float(h));
        } else if (idx < totalW + totalA) {
            int i = idx - totalW;              // A is [E,R,D_IN]: row (e*R+r), col d
            float s = S_a[i];
            float v = A[i] * (1.0f / (1.0f + expf(-s)));
            __nv_bfloat16 h = __float2bfloat16_rn(v);
            g_Whi[totalW + i] = h;
            g_Wlo[totalW + i] = __float2bfloat16_rn(v - __bfloat162float(h));
        } else {
            int i = idx - totalW - totalA;     // B is [E, D_OUT, R]
            int e   = i / (D_OUT * RANK);
            int rem = i - e * (D_OUT * RANK);
            int o   = rem / RANK;
            int r   = rem - o * RANK;
            float s = S_b[i];
            float v = B[i] * (1.0f / (1.0f + expf(-s)));
            g_Bh[o * ER + e * RANK + r] = __float2bfloat16_rn(v);
        }
    }
}

// ---------------- router + X conversion fused ----------------
// One warp per token: computes top-2 softmax gate AND writes X as bf16 hi/lo.
__global__ void router_kernel(const float4* __restrict__ x4,
                              const float4* __restrict__ rw4,
                              const float* __restrict__ router_b) {
    const int warp = (blockIdx.x * blockDim.x + threadIdx.x) >> 5;
    const int lane = threadIdx.x & 31;
    if (warp >= T_TOK) return;

    float acc[N_EXP];
#pragma unroll
    for (int e = 0; e < N_EXP; e++) acc[e] = 0.0f;

    const float4* xrow = x4 + (size_t)warp * (D_IN / 4);
    __nv_bfloat162* xh2 = (__nv_bfloat162*)(g_Xhi + (size_t)warp * D_IN);
    __nv_bfloat162* xl2 = (__nv_bfloat162*)(g_Xlo + (size_t)warp * D_IN);
#pragma unroll 2
    for (int j = lane; j < D_IN / 4; j += 32) {
        float4 xv = xrow[j];
#pragma unroll
        for (int e = 0; e < N_EXP; e++) {
            float4 wv = rw4[e * (D_IN / 4) + j];
            acc[e] += xv.x * wv.x + xv.y * wv.y + xv.z * wv.z + xv.w * wv.w;
        }
        // hi/lo split store
        __nv_bfloat16 h0 = __float2bfloat16_rn(xv.x);
        __nv_bfloat16 h1 = __float2bfloat16_rn(xv.y);
        __nv_bfloat16 h2 = __float2bfloat16_rn(xv.z);
        __nv_bfloat16 h3 = __float2bfloat16_rn(xv.w);
        xh2[2 * j]     = __halves2bfloat162(h0, h1);
        xh2[2 * j + 1] = __halves2bfloat162(h2, h3);
        xl2[2 * j]     = __halves2bfloat162(
            __float2bfloat16_rn(xv.x - __bfloat162float(h0)),
            __float2bfloat16_rn(xv.y - __bfloat162float(h1)));
        xl2[2 * j + 1] = __halves2bfloat162(
            __float2bfloat16_rn(xv.z - __bfloat162float(h2)),
            __float2bfloat16_rn(xv.w - __bfloat162float(h3)));
    }
#pragma unroll
    for (int e = 0; e < N_EXP; e++) {
#pragma unroll
        for (int off = 16; off; off >>= 1)
            acc[e] += __shfl_xor_sync(0xffffffffu, acc[e], off);
        acc[e] += router_b[e];
    }

    float mx = acc[0];
#pragma unroll
    for (int e = 1; e < N_EXP; e++) mx = fmaxf(mx, acc[e]);
    float p[N_EXP];
    float sum = 0.0f;
#pragma unroll
    for (int e = 0; e < N_EXP; e++) { p[e] = expf(acc[e] - mx); sum += p[e]; }
    float inv = 1.0f / sum;

    int i1 = 0; float v1 = p[0];
#pragma unroll
    for (int e = 1; e < N_EXP; e++) if (p[e] > v1) { v1 = p[e]; i1 = e; }
    int i2 = -1; float v2 = -1.0f;
#pragma unroll
    for (int e = 0; e < N_EXP; e++) if (e != i1 && p[e] > v2) { v2 = p[e]; i2 = e; }

    if (lane < N_EXP) {
        float g = (lane == i1) ? v1 * inv : (lane == i2) ? v2 * inv : 0.0f;
        g_gate[warp * N_EXP + lane] = g;
    }
}

// ---------------- mma.sync GEMM: C[128x128] = A[128,K] @ B[128,K]^T ----------------
// THREE=true : bf16 hi/lo 3-pass (Ah*Bh + Al*Bh + Ah*Bl), fp32 accum.
// THREE=false: single-pass bf16.
// MODE 0, THREE, NX0=0 : base  -> out = acc + bias          (A=X, B=Wcat, K=1024)
// MODE 0, !THREE, NX0=8: LoRA  -> g_H = bf16(acc * gate)    (A=X, B=Wcat rows 1024+, K=1024)
// MODE 1, !THREE, NX0=0: delta -> out += acc                (A=g_H, B=g_Bh, K=256)
#define ROWB  80u          // 32 bf16 = 64B payload + 16B pad (conflict-free LDSM)
#define TILEB (128u * ROWB)

template <int MODE, bool THREE, int NX0>
__global__ void __launch_bounds__(256)
mma_gemm(const float* __restrict__ bias, float* __restrict__ Cout) {
    constexpr int K    = (MODE == 0) ? 1024 : ER;
    constexpr int NSTG = K / 32;
    constexpr uint32_t OFF_AH = 0;
    constexpr uint32_t OFF_AL = TILEB;                       // THREE only
    constexpr uint32_t OFF_BH = THREE ? 2 * TILEB : TILEB;
    constexpr uint32_t OFF_BL = 3 * TILEB;                   // THREE only
    constexpr uint32_t SS     = THREE ? 4 * TILEB : 2 * TILEB;  // stage stride

    extern __shared__ __align__(128) char smem[];
    const uint32_t sb = smem_u32(smem);
    const int tid  = threadIdx.x;
    const int lane = tid & 31;
    const int warp = tid >> 5;
    const int wm = warp >> 2;          // 0..1
    const int wn = warp & 3;           // 0..3
    const int m0 = blockIdx.y * 128;
    const int n0 = (blockIdx.x + NX0) * 128;

    const __nv_bfloat16* __restrict__ Agh = (MODE == 0) ? g_Xhi : g_H;
    const __nv_bfloat16* __restrict__ Bgh = (MODE == 0) ? g_Whi : g_Bh;

    // per-thread cp.async slots: chunk c -> row c>>2, 16B-chunk c&3
    const int r0c = tid >> 2, k0c = tid & 3;

    float acc[4][4][4];
#pragma unroll
    for (int a = 0; a < 4; a++)
#pragma unroll
        for (int b = 0; b < 4; b++)
#pragma unroll
            for (int c = 0; c < 4; c++) acc[a][b][c] = 0.0f;

    // ---- stage loader ----
    auto load_stage = [&](int stg, int k0) {
#pragma unroll
        for (int s = 0; s < 2; s++) {
            int row = r0c + s * 64;
            uint32_t so = (uint32_t)stg * SS + (uint32_t)row * ROWB + (uint32_t)k0c * 16;
            size_t ge = (size_t)k0 + k0c * 8;
            cp16(sb + OFF_AH + so, Agh + (size_t)(m0 + row) * K + ge);
            cp16(sb + OFF_BH + so, Bgh + (size_t)(n0 + row) * K + ge);
            if (THREE) {
                cp16(sb + OFF_AL + so, g_Xlo + (size_t)(m0 + row) * K + ge);
                cp16(sb + OFF_BL + so, g_Wlo + (size_t)(n0 + row) * K + ge);
            }
        }
    };

    load_stage(0, 0);
    CP_COMMIT();

    int buf = 0;
    for (int st = 0; st < NSTG; st++) {
        if (st + 1 < NSTG) load_stage(buf ^ 1, (st + 1) * 32);
        CP_COMMIT();
        CP_WAIT1();
        __syncthreads();

        const uint32_t sbase = sb + (uint32_t)buf * SS;
        const uint32_t arow  = (uint32_t)(wm * 64 + (lane & 15));
        const uint32_t brow  = (uint32_t)(wn * 32 + (lane & 15));
#pragma unroll
        for (int ks = 0; ks < 2; ks++) {
            const uint32_t kby = (uint32_t)(ks * 32 + (lane >> 4) * 16);
            uint32_t ah[4][4], bh[4][2];
#pragma unroll
            for (int mf = 0; mf < 4; mf++)
                ldsm4(ah[mf], sbase + OFF_AH + (arow + mf * 16) * ROWB + kby);
#pragma unroll
            for (int p = 0; p < 2; p++) {
                uint32_t r[4];
                ldsm4(r, sbase + OFF_BH + (brow + p * 16) * ROWB + kby);
                bh[2 * p][0] = r[0]; bh[2 * p + 1][0] = r[1];
                bh[2 * p][1] = r[2]; bh[2 * p + 1][1] = r[3];
            }
#pragma unroll
            for (int mf = 0; mf < 4; mf++)
#pragma unroll
                for (int nf = 0; nf < 4; nf++)
                    mma_bf16(acc[mf][nf], ah[mf], bh[nf]);

            if (THREE) {
                uint32_t al[4][4], bl[4][2];
#pragma unroll
                for (int mf = 0; mf < 4; mf++)
                    ldsm4(al[mf], sbase + OFF_AL + (arow + mf * 16) * ROWB + kby);
#pragma unroll
                for (int p = 0; p < 2; p++) {
                    uint32_t r[4];
                    ldsm4(r, sbase + OFF_BL + (brow + p * 16) * ROWB + kby);
                    bl[2 * p][0] = r[0]; bl[2 * p + 1][0] = r[1];
                    bl[2 * p][1] = r[2]; bl[2 * p + 1][1] = r[3];
                }
#pragma unroll
                for (int mf = 0; mf < 4; mf++)
#pragma unroll
                    for (int nf = 0; nf < 4; nf++) {
                        mma_bf16(acc[mf][nf], al[mf], bh[nf]);
                        mma_bf16(acc[mf][nf], ah[mf], bl[nf]);
                    }
            }
        }
        __syncthreads();
        buf ^= 1;
    }

    // ---------------- epilogue ----------------
    const int mr  = lane >> 2;
    const int nc2 = (lane & 3) * 2;
#pragma unroll
    for (int mf = 0; mf < 4; mf++) {
#pragma unroll
        for (int nf = 0; nf < 4; nf++) {
            const int m = m0 + wm * 64 + mf * 16 + mr;
            const int n = n0 + wn * 32 + nf * 8 + nc2;
            float* a = acc[mf][nf];
            if (MODE == 0 && THREE) {
                float2 bb = *(const float2*)(bias + n);
                float2 o0 = {a[0] + bb.x, a[1] + bb.y};
                float2 o1 = {a[2] + bb.x, a[3] + bb.y};
                *(float2*)(Cout + (size_t)m * D_OUT + n)       = o0;
                *(float2*)(Cout + (size_t)(m + 8) * D_OUT + n) = o1;
            } else if (MODE == 0) {
                const int er = n - D_OUT;
                const int ex = er >> 5;
                float gA = g_gate[m * N_EXP + ex];
                float gB = g_gate[(m + 8) * N_EXP + ex];
                *(__nv_bfloat162*)(g_H + (size_t)m * ER + er) =
                    __halves2bfloat162(__float2bfloat16_rn(a[0] * gA),
                                       __float2bfloat16_rn(a[1] * gA));
                *(__nv_bfloat162*)(g_H + (size_t)(m + 8) * ER + er) =
                    __halves2bfloat162(__float2bfloat16_rn(a[2] * gB),
                                       __float2bfloat16_rn(a[3] * gB));
            } else {
                float2 o0 = *(float2*)(Cout + (size_t)m * D_OUT + n);
                float2 o1 = *(float2*)(Cout + (size_t)(m + 8) * D_OUT + n);
                o0.x += a[0]; o0.y += a[1];
                o1.x += a[2]; o1.y += a[3];
                *(float2*)(Cout + (size_t)m * D_OUT + n)       = o0;
                *(float2*)(Cout + (size_t)(m + 8) * D_OUT + n) = o1;
            }
        }
    }
}

// ---------------- launcher ----------------
extern "C" void kernel_launch(void* const* d_in, const int* in_sizes, int n_in,
                              void* d_out, int out_size) {
    const float* x        = (const float*)d_in[0];
    const float* base_W   = (const float*)d_in[1];
    const float* base_b   = (const float*)d_in[2];
    const float* router_W = (const float*)d_in[3];
    const float* router_b = (const float*)d_in[4];
    const float* A        = (const float*)d_in[5];
    const float* S_a      = (const float*)d_in[6];
    const float* B        = (const float*)d_in[7];
    const float* S_b      = (const float*)d_in[8];
    float* out = (float*)d_out;

    const int SM3 = 2 * 4 * TILEB;   // 81920 B (3-pass, double buffered)
    const int SM1 = 2 * 2 * TILEB;   // 40960 B (1-pass)
    cudaFuncSetAttribute((const void*)mma_gemm<0, true, 0>,
                         cudaFuncAttributeMaxDynamicSharedMemorySize, SM3);
    cudaFuncSetAttribute((const void*)mma_gemm<0, false, 8>,
                         cudaFuncAttributeMaxDynamicSharedMemorySize, SM1);
    cudaFuncSetAttribute((const void*)mma_gemm<1, false, 0>,
                         cudaFuncAttributeMaxDynamicSharedMemorySize, SM1);

    // 1) weights -> bf16 (W hi/lo, Bcat hi)
    prep_kernel<<<1024, 512>>>(base_W, A, S_a, B, S_b);
    // 2) router (gates) + X -> bf16 hi/lo, fused
    router_kernel<<<T_TOK / 8, 256>>>((const float4*)x, (const float4*)router_W, router_b);
    // 3) base GEMM (3-pass): out = X @ W^T + bias
    mma_gemm<0, true, 0><<<dim3(8, 128), 256, SM3>>>(base_b, out);
    // 4) LoRA GEMM (1-pass): g_H = gate * (X @ A_t^T)
    mma_gemm<0, false, 8><<<dim3(2, 128), 256, SM1>>>(nullptr, out);
    // 5) delta GEMM (1-pass): out += g_H @ B_t^T
    mma_gemm<1, false, 0><<<dim3(8, 128), 256, SM1>>>(nullptr, out);
}